// round 4
// baseline (speedup 1.0000x reference)
#include <cuda_runtime.h>
#include <cstdint>

// ---------------------------------------------------------------------------
// CharLSTM  (B=512, T=512, VOCAB=256, EMB=32, HID=128)
//
// Pipeline:
//   k_detect : decide whether `inputs` buffer is int64 or int32
//   k_embw   : embW[v][hcol] = float4(i,f,g,o) = emb[v]@W_ih^T + b_ih + b_hh
//              (input projection folded into a 256-entry table)
//   k_lstm   : 128 persistent CTAs x 4 batch rows, 512 timesteps.
//              gates = h @ W_hh^T via fp32x2 FFMA2;
//              W_hh split: k[0,80) in smem (160KB), k[80,128) in registers.
//              Epilogue (sigmoid/tanh via EX2+RCP) + classifier in-block.
// ---------------------------------------------------------------------------

#define VOCAB 256
#define EMB   32
#define HID   128
#define G4    512      // 4*HID
#define BATCH 512
#define TLEN  512

#define NBLK  128
#define RPB   4        // batch rows per block
#define NTHR  256      // threads in main kernel (8 warps)

#define K2_SMEM 40     // k-pairs held in smem  (k in [0,80))
#define K2_REG  24     // k-pairs held in regs  (k in [80,128))
// K2_SMEM + K2_REG == 64  (HID/2)

// smem layout (bytes)
#define WP_BYTES    (K2_SMEM * G4 * 8)        // 163840
#define HP_BYTES    (64 * RPB * 8)            // 2048
#define GATES_BYTES (G4 * RPB * 4)            // 8192
#define TOKS_BYTES  (RPB * TLEN * 4)          // 8192
#define SMEM_BYTES  (WP_BYTES + HP_BYTES + GATES_BYTES + TOKS_BYTES)  // 182272

__device__ int    g_is64;
__device__ float4 g_embW[VOCAB * HID];        // [v][hcol] = (i,f,g,o) preact addend

// ---- f32x2 helpers --------------------------------------------------------
__device__ __forceinline__ unsigned long long ffma2(unsigned long long a,
                                                    unsigned long long b,
                                                    unsigned long long c) {
    unsigned long long d;
    asm("fma.rn.f32x2 %0, %1, %2, %3;" : "=l"(d) : "l"(a), "l"(b), "l"(c));
    return d;
}
__device__ __forceinline__ float lo32(unsigned long long v) {
    return __uint_as_float((unsigned int)v);
}
__device__ __forceinline__ float hi32(unsigned long long v) {
    return __uint_as_float((unsigned int)(v >> 32));
}

// ---- accurate fast activations (EX2/RCP based, ~2 ulp) --------------------
__device__ __forceinline__ float sigf(float x) {
    return __fdividef(1.0f, 1.0f + __expf(-x));       // handles +-inf limits
}
__device__ __forceinline__ float tanhf_fast(float x) {
    // tanh(x) = 1 - 2/(e^{2x}+1); exp overflow -> inf -> 1, exp->0 -> -1 (correct)
    return 1.0f - __fdividef(2.0f, __expf(2.0f * x) + 1.0f);
}

// ---------------------------------------------------------------------------
// Kernel 0: int64-vs-int32 detection.
// int64 little-endian tokens (0..255) => every odd 32-bit word is 0.
// Only reads words [0, 8192) -- in bounds for both layouts (>=262144 words).
// ---------------------------------------------------------------------------
__global__ void k_detect(const unsigned int* __restrict__ w) {
    __shared__ int bad;
    if (threadIdx.x == 0) bad = 0;
    __syncthreads();
    int mybad = 0;
    for (int i = threadIdx.x; i < 4096; i += blockDim.x) {
        if (w[2 * i + 1] != 0u) mybad = 1;
    }
    if (mybad) bad = 1;
    __syncthreads();
    if (threadIdx.x == 0) g_is64 = bad ? 0 : 1;
}

// ---------------------------------------------------------------------------
// Kernel 1: embW[v][hcol] = (b_ih + b_hh + emb[v] @ W_ih^T) for gates i,f,g,o
// ---------------------------------------------------------------------------
__global__ void k_embw(const float* __restrict__ emb,
                       const float* __restrict__ W_ih,
                       const float* __restrict__ b_ih,
                       const float* __restrict__ b_hh) {
    __shared__ float e_s[EMB];
    int v  = blockIdx.x;
    int hc = threadIdx.x;                 // 0..127
    if (threadIdx.x < EMB) e_s[threadIdx.x] = emb[v * EMB + threadIdx.x];
    __syncthreads();
    float acc[4];
#pragma unroll
    for (int q = 0; q < 4; q++) {
        int g = q * HID + hc;
        float s = b_ih[g] + b_hh[g];
        const float* wr = W_ih + g * EMB;
#pragma unroll
        for (int e = 0; e < EMB; e++) s += wr[e] * e_s[e];
        acc[q] = s;
    }
    g_embW[v * HID + hc] = make_float4(acc[0], acc[1], acc[2], acc[3]);
}

// ---------------------------------------------------------------------------
// Kernel 2: persistent LSTM + classifier
// ---------------------------------------------------------------------------
extern __shared__ unsigned char smem_raw[];

__global__ void __launch_bounds__(NTHR, 1)
k_lstm(const void* __restrict__ inputs,
       const float* __restrict__ W_hh,
       const float* __restrict__ W_cls,
       const float* __restrict__ b_cls,
       float* __restrict__ out) {

    unsigned long long* wP  = (unsigned long long*)smem_raw;                       // [K2_SMEM][512]
    unsigned long long* hP  = (unsigned long long*)(smem_raw + WP_BYTES);          // [64][4]
    float*              gts = (float*)(smem_raw + WP_BYTES + HP_BYTES);            // [512][4]
    int*                tok = (int*)(smem_raw + WP_BYTES + HP_BYTES + GATES_BYTES);// [4][512]
    float*              hPf = (float*)hP;

    const int tid   = threadIdx.x;
    const int rbase = blockIdx.x * RPB;

    // ---- load token slab for this block's 4 rows -------------------------
    const int is64 = g_is64;
    for (int i = tid; i < RPB * TLEN; i += NTHR) {
        int r = i >> 9;                  // /512
        int t = i & (TLEN - 1);
        long long gi = (long long)(rbase + r) * TLEN + t;
        int tk;
        if (is64) tk = (int)((const unsigned int*)inputs)[2 * gi];
        else      tk = ((const int*)inputs)[gi];
        tok[r * TLEN + t] = tk & 255;
    }

    // ---- stage W_hh: smem part (k-pairs 0..39) ---------------------------
    // W_hh row-major [512][128] floats -> pairs: Wv[g*64 + k2]
    const unsigned long long* Wv = (const unsigned long long*)W_hh;
    for (int i = tid; i < K2_SMEM * G4; i += NTHR) {
        int k2 = i >> 9;
        int g  = i & 511;
        wP[k2 * G4 + g] = Wv[g * 64 + k2];
    }

    // ---- register part (k-pairs 40..63) for this thread's 2 gate columns -
    unsigned long long wr0[K2_REG], wr1[K2_REG];
    {
        const unsigned long long* p0 = Wv + (2 * tid)     * 64 + K2_SMEM;
        const unsigned long long* p1 = Wv + (2 * tid + 1) * 64 + K2_SMEM;
#pragma unroll
        for (int j = 0; j < K2_REG; j++) { wr0[j] = p0[j]; wr1[j] = p1[j]; }
    }

    // ---- zero h state ----------------------------------------------------
    for (int i = tid; i < 64 * RPB; i += NTHR) hP[i] = 0ULL;

    // epilogue items: item0 = tid, item1 = tid+256; item -> (r = item&3, hcol = item>>2)
    const int i0r = tid & 3;
    const int i0h = tid >> 2;            // 0..63
    const int i1h = i0h + 64;            // 64..127
    float c0 = 0.0f, c1 = 0.0f;

    __syncthreads();

    const unsigned long long* wp_t = wP + 2 * tid;
    const int* tr0 = tok + i0r * TLEN;   // item rows share r = tid&3

    // =========================== time loop ================================
    for (int t = 0; t < TLEN; t++) {
        // prefetch embW addends for epilogue (hidden under GEMM latency)
        int tk = tr0[t];
        float4 e0 = g_embW[tk * HID + i0h];
        float4 e1 = g_embW[tk * HID + i1h];

        // ---- GEMM: gates[c, r] += sum_k W[c,k] * h[r,k], f32x2 over k ----
        unsigned long long a00 = 0, a01 = 0, a02 = 0, a03 = 0;
        unsigned long long a10 = 0, a11 = 0, a12 = 0, a13 = 0;

#pragma unroll
        for (int k2 = 0; k2 < K2_SMEM; k2++) {
            ulonglong2 wv  = *(const ulonglong2*)(wp_t + k2 * G4);
            ulonglong2 h01 = *(const ulonglong2*)(hP + k2 * 4);
            ulonglong2 h23 = *(const ulonglong2*)(hP + k2 * 4 + 2);
            a00 = ffma2(wv.x, h01.x, a00);
            a01 = ffma2(wv.x, h01.y, a01);
            a02 = ffma2(wv.x, h23.x, a02);
            a03 = ffma2(wv.x, h23.y, a03);
            a10 = ffma2(wv.y, h01.x, a10);
            a11 = ffma2(wv.y, h01.y, a11);
            a12 = ffma2(wv.y, h23.x, a12);
            a13 = ffma2(wv.y, h23.y, a13);
        }
#pragma unroll
        for (int j = 0; j < K2_REG; j++) {
            int k2 = K2_SMEM + j;
            ulonglong2 h01 = *(const ulonglong2*)(hP + k2 * 4);
            ulonglong2 h23 = *(const ulonglong2*)(hP + k2 * 4 + 2);
            a00 = ffma2(wr0[j], h01.x, a00);
            a01 = ffma2(wr0[j], h01.y, a01);
            a02 = ffma2(wr0[j], h23.x, a02);
            a03 = ffma2(wr0[j], h23.y, a03);
            a10 = ffma2(wr1[j], h01.x, a10);
            a11 = ffma2(wr1[j], h01.y, a11);
            a12 = ffma2(wr1[j], h23.x, a12);
            a13 = ffma2(wr1[j], h23.y, a13);
        }

        // horizontal add (even-k lane + odd-k lane), store gates [col][r]
        float4 gv0, gv1;
        gv0.x = lo32(a00) + hi32(a00);
        gv0.y = lo32(a01) + hi32(a01);
        gv0.z = lo32(a02) + hi32(a02);
        gv0.w = lo32(a03) + hi32(a03);
        gv1.x = lo32(a10) + hi32(a10);
        gv1.y = lo32(a11) + hi32(a11);
        gv1.z = lo32(a12) + hi32(a12);
        gv1.w = lo32(a13) + hi32(a13);
        *(float4*)(gts + 8 * tid)     = gv0;   // col 2*tid,   rows 0..3
        *(float4*)(gts + 8 * tid + 4) = gv1;   // col 2*tid+1, rows 0..3
        __syncthreads();

        // ---- LSTM elementwise epilogue: 2 items per thread ---------------
        {
            float ip = gts[4 * i0h             + i0r] + e0.x;
            float fp = gts[4 * (HID + i0h)     + i0r] + e0.y;
            float gp = gts[4 * (2 * HID + i0h) + i0r] + e0.z;
            float op = gts[4 * (3 * HID + i0h) + i0r] + e0.w;
            float si = sigf(ip), sf = sigf(fp);
            float sg = tanhf_fast(gp), so = sigf(op);
            c0 = sf * c0 + si * sg;
            float hv = so * tanhf_fast(c0);
            hPf[(i0h >> 1) * 8 + i0r * 2 + (i0h & 1)] = hv;
        }
        {
            float ip = gts[4 * i1h             + i0r] + e1.x;
            float fp = gts[4 * (HID + i1h)     + i0r] + e1.y;
            float gp = gts[4 * (2 * HID + i1h) + i0r] + e1.z;
            float op = gts[4 * (3 * HID + i1h) + i0r] + e1.w;
            float si = sigf(ip), sf = sigf(fp);
            float sg = tanhf_fast(gp), so = sigf(op);
            c1 = sf * c1 + si * sg;
            float hv = so * tanhf_fast(c1);
            hPf[(i1h >> 1) * 8 + i0r * 2 + (i1h & 1)] = hv;
        }
        __syncthreads();
    }

    // =========================== classifier ===============================
    // linearize h_last into gts (reuse): hlin[r*HID + k]
    for (int i = tid; i < RPB * HID; i += NTHR) {
        int r = i >> 7;          // /128
        int k = i & (HID - 1);
        gts[i] = hPf[(k >> 1) * 8 + r * 2 + (k & 1)];
    }
    __syncthreads();

    {
        int v = tid;             // 0..255 vocab columns
        float bb = b_cls[v];
        float acc0 = bb, acc1 = bb, acc2 = bb, acc3 = bb;
        const float4* wc = (const float4*)(W_cls + v * HID);
        const float4* h0 = (const float4*)(gts + 0 * HID);
        const float4* h1 = (const float4*)(gts + 1 * HID);
        const float4* h2 = (const float4*)(gts + 2 * HID);
        const float4* h3 = (const float4*)(gts + 3 * HID);
#pragma unroll 8
        for (int k4 = 0; k4 < HID / 4; k4++) {
            float4 w  = wc[k4];
            float4 v0 = h0[k4], v1 = h1[k4], v2 = h2[k4], v3 = h3[k4];
            acc0 += w.x * v0.x + w.y * v0.y + w.z * v0.z + w.w * v0.w;
            acc1 += w.x * v1.x + w.y * v1.y + w.z * v1.z + w.w * v1.w;
            acc2 += w.x * v2.x + w.y * v2.y + w.z * v2.z + w.w * v2.w;
            acc3 += w.x * v3.x + w.y * v3.y + w.z * v3.z + w.w * v3.w;
        }
        out[(rbase + 0) * VOCAB + v] = acc0;
        out[(rbase + 1) * VOCAB + v] = acc1;
        out[(rbase + 2) * VOCAB + v] = acc2;
        out[(rbase + 3) * VOCAB + v] = acc3;
    }
}

// ---------------------------------------------------------------------------
// Host launcher. Inputs mapped by element count (b_ih/b_hh ambiguity is
// harmless: they are only ever used as a sum).
// ---------------------------------------------------------------------------
extern "C" void kernel_launch(void* const* d_in, const int* in_sizes, int n_in,
                              void* d_out, int out_size) {
    const void*  inputs = nullptr;
    const float* emb = nullptr;
    const float* W_ih = nullptr;
    const float* W_hh = nullptr;
    const float* b_a = nullptr;     // first 512-sized bias
    const float* b_b = nullptr;     // second 512-sized bias
    const float* W_cls = nullptr;
    const float* b_cls = nullptr;

    for (int i = 0; i < n_in; i++) {
        int sz = in_sizes[i];
        const void* p = d_in[i];
        switch (sz) {
            case BATCH * TLEN:   inputs = p;                 break;  // 262144
            case VOCAB * EMB:    emb    = (const float*)p;   break;  // 8192
            case G4 * EMB:       W_ih   = (const float*)p;   break;  // 16384
            case G4 * HID:       W_hh   = (const float*)p;   break;  // 65536
            case VOCAB * HID:    W_cls  = (const float*)p;   break;  // 32768
            case VOCAB:          b_cls  = (const float*)p;   break;  // 256
            case G4:                                                  // 512 (x2)
                if (!b_a) b_a = (const float*)p; else b_b = (const float*)p;
                break;
            default: break;
        }
    }
    if (!inputs || !emb || !W_ih || !W_hh || !b_a || !b_b || !W_cls || !b_cls)
        return;

    cudaFuncSetAttribute(k_lstm, cudaFuncAttributeMaxDynamicSharedMemorySize,
                         SMEM_BYTES);

    k_detect<<<1, 256>>>((const unsigned int*)inputs);
    k_embw<<<VOCAB, HID>>>(emb, W_ih, b_a, b_b);
    k_lstm<<<NBLK, NTHR, SMEM_BYTES>>>(inputs, W_hh, W_cls, b_cls,
                                       (float*)d_out);
}

// round 5
// speedup vs baseline: 1.2673x; 1.2673x over previous
#include <cuda_runtime.h>
#include <cstdint>

// ---------------------------------------------------------------------------
// CharLSTM  (B=512, T=512, VOCAB=256, EMB=32, HID=128)
//
//   k_prep : block 0..255 -> embW[v][hcol] = emb[v]@W_ih^T + b_ih + b_hh
//            block 256    -> int64-vs-int32 input detection
//   k_lstm : 128 persistent CTAs x 4 batch rows x 512 steps.
//            Thread = (hcol, 2 rows); accumulates ALL FOUR gate preacts for
//            its own epilogue items -> no gates exchange, ONE barrier/step,
//            double-buffered h. W_hh: k2[0,50) in smem (200KB, LDS.128),
//            k2[50,64) in regs. GEMM via fp32x2 FFMA2.
// ---------------------------------------------------------------------------

#define VOCAB 256
#define EMB   32
#define HID   128
#define G4    512
#define BATCH 512
#define TLEN  512

#define NBLK  128
#define RPB   4
#define NTHR  256

#define K2S   50          // k-pairs in smem
#define K4S   25          // 2-k2 chunks in smem
#define K2R   14          // k-pairs in regs (per thread, per gate)

// smem layout (bytes)
#define WS_BYTES   (K4S * G4 * 16)     // 204800
#define HB_BYTES   (2 * G4 * 4)        // 4096  (double-buffered h: [2][512]f)
#define TOK_BYTES  (RPB * TLEN * 4)    // 8192
#define SMEM_BYTES (WS_BYTES + HB_BYTES + TOK_BYTES)   // 217088

__device__ int    g_is64;
__device__ float4 g_embW[VOCAB * HID];   // [v][hcol] = (i,f,g,o) addend

// ---- f32x2 helpers --------------------------------------------------------
__device__ __forceinline__ unsigned long long ffma2(unsigned long long a,
                                                    unsigned long long b,
                                                    unsigned long long c) {
    unsigned long long d;
    asm("fma.rn.f32x2 %0, %1, %2, %3;" : "=l"(d) : "l"(a), "l"(b), "l"(c));
    return d;
}
__device__ __forceinline__ float lo32(unsigned long long v) {
    return __uint_as_float((unsigned int)v);
}
__device__ __forceinline__ float hi32(unsigned long long v) {
    return __uint_as_float((unsigned int)(v >> 32));
}

// ---- activations (EX2/RCP based, ~2 ulp) ----------------------------------
__device__ __forceinline__ float sigf(float x) {
    return __fdividef(1.0f, 1.0f + __expf(-x));
}
__device__ __forceinline__ float tanhf_fast(float x) {
    return 1.0f - __fdividef(2.0f, __expf(2.0f * x) + 1.0f);
}

// ---------------------------------------------------------------------------
// Prep kernel: embW table (blocks 0..255) + input dtype detect (block 256)
// ---------------------------------------------------------------------------
__global__ void k_prep(const unsigned int* __restrict__ words,
                       const float* __restrict__ emb,
                       const float* __restrict__ W_ih,
                       const float* __restrict__ b_a,
                       const float* __restrict__ b_b) {
    if (blockIdx.x == VOCAB) {
        // int64 LE tokens (0..255) => every odd 32-bit word is 0.
        // Reads words [0,8192) -- in bounds for both layouts.
        __shared__ int bad;
        if (threadIdx.x == 0) bad = 0;
        __syncthreads();
        int my = 0;
        for (int i = threadIdx.x; i < 4096; i += 128)
            if (words[2 * i + 1] != 0u) my = 1;
        if (my) bad = 1;
        __syncthreads();
        if (threadIdx.x == 0) g_is64 = bad ? 0 : 1;
        return;
    }
    __shared__ float e_s[EMB];
    int v  = blockIdx.x;
    int hc = threadIdx.x;                 // 0..127
    if (threadIdx.x < EMB) e_s[threadIdx.x] = emb[v * EMB + threadIdx.x];
    __syncthreads();
    float acc[4];
#pragma unroll
    for (int q = 0; q < 4; q++) {
        int g = q * HID + hc;
        float s = b_a[g] + b_b[g];
        const float* wr = W_ih + g * EMB;
#pragma unroll
        for (int e = 0; e < EMB; e++) s += wr[e] * e_s[e];
        acc[q] = s;
    }
    g_embW[v * HID + hc] = make_float4(acc[0], acc[1], acc[2], acc[3]);
}

// ---------------------------------------------------------------------------
// Main persistent LSTM + classifier
// ---------------------------------------------------------------------------
extern __shared__ unsigned char smem_raw[];

__global__ void __launch_bounds__(NTHR, 1)
k_lstm(const void* __restrict__ inputs,
       const float* __restrict__ W_hh,
       const float* __restrict__ W_cls,
       const float* __restrict__ b_cls,
       float* __restrict__ out) {

    ulonglong2*         wS  = (ulonglong2*)smem_raw;                 // [K4S][512]
    float*              hbF = (float*)(smem_raw + WS_BYTES);         // [2][512]
    unsigned long long* hbU = (unsigned long long*)hbF;
    int*                tok = (int*)(smem_raw + WS_BYTES + HB_BYTES);// [4][512]

    const int tid   = threadIdx.x;
    const int rbase = blockIdx.x * RPB;

    // ---- token slab ------------------------------------------------------
    const int is64 = g_is64;
    for (int i = tid; i < RPB * TLEN; i += NTHR) {
        int r = i >> 9;
        int t = i & (TLEN - 1);
        long long gi = (long long)(rbase + r) * TLEN + t;
        int tk;
        if (is64) tk = (int)((const unsigned int*)inputs)[2 * gi];
        else      tk = ((const int*)inputs)[gi];
        tok[r * TLEN + t] = tk & 255;
    }

    // ---- stage W_hh smem part: wS[k4][g] = 16B chunk (k2=2k4,2k4+1) ------
    const ulonglong2* W4 = (const ulonglong2*)W_hh;   // [512][32] 16B chunks
    for (int i = tid; i < K4S * G4; i += NTHR) {
        int k4 = i >> 9;
        int g  = i & 511;
        wS[k4 * G4 + g] = W4[g * 32 + k4];
    }

    // ---- register weights: k2 in [K2S,64), all 4 gates, this hcol --------
    const int hcol = tid >> 1;           // 0..127
    const int rp   = tid & 1;            // row pair: rows {2rp, 2rp+1}
    const int r0   = 2 * rp;

    unsigned long long wr[4][K2R];
    {
        const unsigned long long* Wv = (const unsigned long long*)W_hh;
#pragma unroll
        for (int q = 0; q < 4; q++) {
            const unsigned long long* p = Wv + (q * HID + hcol) * 64 + K2S;
#pragma unroll
            for (int j = 0; j < K2R; j++) wr[q][j] = p[j];
        }
    }

    // ---- zero h buffer 0 -------------------------------------------------
    for (int i = tid; i < G4; i += NTHR) hbF[i] = 0.0f;

    float c0 = 0.0f, c1 = 0.0f;
    __syncthreads();

    const int* tp0 = tok + r0 * TLEN;
    const int* tp1 = tok + (r0 + 1) * TLEN;
    const ulonglong2* wp = wS + hcol;

    // =========================== time loop ================================
    for (int t = 0; t < TLEN; t++) {
        const int cur = t & 1;

        // prefetch epilogue addends (hidden under GEMM)
        float4 e0 = g_embW[tp0[t] * HID + hcol];
        float4 e1 = g_embW[tp1[t] * HID + hcol];

        const ulonglong2* hB = (const ulonglong2*)(hbU + cur * 256);

        unsigned long long a00 = 0, a01 = 0, a10 = 0, a11 = 0;
        unsigned long long a20 = 0, a21 = 0, a30 = 0, a31 = 0;

#pragma unroll
        for (int k4 = 0; k4 < K4S; k4++) {
            ulonglong2 ha = hB[(2 * k4) * 2 + rp];       // k2a, rows r0,r0+1
            ulonglong2 hb = hB[(2 * k4 + 1) * 2 + rp];   // k2b
            ulonglong2 w0 = wp[k4 * G4 + 0 * HID];
            ulonglong2 w1 = wp[k4 * G4 + 1 * HID];
            ulonglong2 w2 = wp[k4 * G4 + 2 * HID];
            ulonglong2 w3 = wp[k4 * G4 + 3 * HID];
            a00 = ffma2(w0.x, ha.x, a00);  a01 = ffma2(w0.x, ha.y, a01);
            a10 = ffma2(w1.x, ha.x, a10);  a11 = ffma2(w1.x, ha.y, a11);
            a20 = ffma2(w2.x, ha.x, a20);  a21 = ffma2(w2.x, ha.y, a21);
            a30 = ffma2(w3.x, ha.x, a30);  a31 = ffma2(w3.x, ha.y, a31);
            a00 = ffma2(w0.y, hb.x, a00);  a01 = ffma2(w0.y, hb.y, a01);
            a10 = ffma2(w1.y, hb.x, a10);  a11 = ffma2(w1.y, hb.y, a11);
            a20 = ffma2(w2.y, hb.x, a20);  a21 = ffma2(w2.y, hb.y, a21);
            a30 = ffma2(w3.y, hb.x, a30);  a31 = ffma2(w3.y, hb.y, a31);
        }
#pragma unroll
        for (int j = 0; j < K2R; j++) {
            ulonglong2 hx = hB[(K2S + j) * 2 + rp];
            a00 = ffma2(wr[0][j], hx.x, a00);  a01 = ffma2(wr[0][j], hx.y, a01);
            a10 = ffma2(wr[1][j], hx.x, a10);  a11 = ffma2(wr[1][j], hx.y, a11);
            a20 = ffma2(wr[2][j], hx.x, a20);  a21 = ffma2(wr[2][j], hx.y, a21);
            a30 = ffma2(wr[3][j], hx.x, a30);  a31 = ffma2(wr[3][j], hx.y, a31);
        }

        // ---- local epilogue: 2 items, gates never leave registers --------
        float* hw = hbF + (cur ^ 1) * G4 + (hcol >> 1) * 8 + (hcol & 1);
        {
            float ip = lo32(a00) + hi32(a00) + e0.x;
            float fp = lo32(a10) + hi32(a10) + e0.y;
            float gp = lo32(a20) + hi32(a20) + e0.z;
            float op = lo32(a30) + hi32(a30) + e0.w;
            float si = sigf(ip), sf = sigf(fp);
            float sg = tanhf_fast(gp), so = sigf(op);
            c0 = sf * c0 + si * sg;
            hw[r0 * 2] = so * tanhf_fast(c0);
        }
        {
            float ip = lo32(a01) + hi32(a01) + e1.x;
            float fp = lo32(a11) + hi32(a11) + e1.y;
            float gp = lo32(a21) + hi32(a21) + e1.z;
            float op = lo32(a31) + hi32(a31) + e1.w;
            float si = sigf(ip), sf = sigf(fp);
            float sg = tanhf_fast(gp), so = sigf(op);
            c1 = sf * c1 + si * sg;
            hw[(r0 + 1) * 2] = so * tanhf_fast(c1);
        }
        __syncthreads();   // h(next) complete -> next step may read it
    }

    // =========================== classifier ===============================
    // final h is in buffer 0 (T even). Linearize into tok area (reused).
    float* hlin = (float*)tok;
    for (int i = tid; i < RPB * HID; i += NTHR) {
        int r = i >> 7;
        int k = i & (HID - 1);
        hlin[i] = hbF[(k >> 1) * 8 + r * 2 + (k & 1)];
    }
    __syncthreads();

    {
        int v = tid;                                  // 0..255 vocab cols
        float bb = b_cls[v];
        float acc0 = bb, acc1 = bb, acc2 = bb, acc3 = bb;
        const float4* wc = (const float4*)(W_cls + v * HID);
        const float4* h0 = (const float4*)(hlin + 0 * HID);
        const float4* h1 = (const float4*)(hlin + 1 * HID);
        const float4* h2 = (const float4*)(hlin + 2 * HID);
        const float4* h3 = (const float4*)(hlin + 3 * HID);
#pragma unroll 8
        for (int k4 = 0; k4 < HID / 4; k4++) {
            float4 w  = wc[k4];
            float4 v0 = h0[k4], v1 = h1[k4], v2 = h2[k4], v3 = h3[k4];
            acc0 += w.x * v0.x + w.y * v0.y + w.z * v0.z + w.w * v0.w;
            acc1 += w.x * v1.x + w.y * v1.y + w.z * v1.z + w.w * v1.w;
            acc2 += w.x * v2.x + w.y * v2.y + w.z * v2.z + w.w * v2.w;
            acc3 += w.x * v3.x + w.y * v3.y + w.z * v3.z + w.w * v3.w;
        }
        out[(rbase + 0) * VOCAB + v] = acc0;
        out[(rbase + 1) * VOCAB + v] = acc1;
        out[(rbase + 2) * VOCAB + v] = acc2;
        out[(rbase + 3) * VOCAB + v] = acc3;
    }
}

// ---------------------------------------------------------------------------
// Host launcher (inputs mapped by element count; bias ambiguity harmless:
// biases only ever used summed).
// ---------------------------------------------------------------------------
extern "C" void kernel_launch(void* const* d_in, const int* in_sizes, int n_in,
                              void* d_out, int out_size) {
    const void*  inputs = nullptr;
    const float* emb = nullptr;
    const float* W_ih = nullptr;
    const float* W_hh = nullptr;
    const float* b_a = nullptr;
    const float* b_b = nullptr;
    const float* W_cls = nullptr;
    const float* b_cls = nullptr;

    for (int i = 0; i < n_in; i++) {
        int sz = in_sizes[i];
        const void* p = d_in[i];
        switch (sz) {
            case BATCH * TLEN:   inputs = p;                 break;
            case VOCAB * EMB:    emb    = (const float*)p;   break;
            case G4 * EMB:       W_ih   = (const float*)p;   break;
            case G4 * HID:       W_hh   = (const float*)p;   break;
            case VOCAB * HID:    W_cls  = (const float*)p;   break;
            case VOCAB:          b_cls  = (const float*)p;   break;
            case G4:
                if (!b_a) b_a = (const float*)p; else b_b = (const float*)p;
                break;
            default: break;
        }
    }
    if (!inputs || !emb || !W_ih || !W_hh || !b_a || !b_b || !W_cls || !b_cls)
        return;

    cudaFuncSetAttribute(k_lstm, cudaFuncAttributeMaxDynamicSharedMemorySize,
                         SMEM_BYTES);

    k_prep<<<VOCAB + 1, 128>>>((const unsigned int*)inputs, emb, W_ih, b_a, b_b);
    k_lstm<<<NBLK, NTHR, SMEM_BYTES>>>(inputs, W_hh, W_cls, b_cls,
                                       (float*)d_out);
}